// round 14
// baseline (speedup 1.0000x reference)
#include <cuda_runtime.h>
#include <cuda_bf16.h>
#include <cstdint>

#define BB 32
#define HH 1024
#define SS 2048
#define VV 32000
#define H3 3072
#define H2 2048
#define ACH 16
#define NCH (SS/ACH)          // 128
#define NS 8                  // K-split partials for GRU GEMMs
#define NQ 8                  // K-split for q GEMM
#define NLG 2                 // K-split per logits half
#define ASMEM ((ACH*HH + HH + ACH) * 4)
#define GSMEM 46080

#define FMA2(acc, a, b) asm("fma.rn.f32x2 %0, %1, %2, %0;" : "+l"(acc) : "l"(a), "l"(b))

__device__ __forceinline__ void mma16816(float* d, const uint32_t* a, const uint32_t* b) {
    asm volatile("mma.sync.aligned.m16n8k16.row.col.f32.bf16.bf16.f32 "
                 "{%0,%1,%2,%3}, {%4,%5,%6,%7}, {%8,%9}, {%0,%1,%2,%3};"
                 : "+f"(d[0]), "+f"(d[1]), "+f"(d[2]), "+f"(d[3])
                 : "r"(a[0]), "r"(a[1]), "r"(a[2]), "r"(a[3]), "r"(b[0]), "r"(b[1]));
}

__device__ __forceinline__ void split1(float x, __nv_bfloat16& hi, __nv_bfloat16& lo) {
    hi = __float2bfloat16(x);
    lo = __float2bfloat16(x - __bfloat162float(hi));
}
__device__ __forceinline__ void split_pack(float a, float b, uint32_t& hi, uint32_t& lo) {
    __nv_bfloat162 h = __floats2bfloat162_rn(a, b);
    __nv_bfloat162 l2 = __floats2bfloat162_rn(a - __bfloat162float(h.x), b - __bfloat162float(h.y));
    hi = *reinterpret_cast<uint32_t*>(&h);
    lo = *reinterpret_cast<uint32_t*>(&l2);
}

// ==================== scratch ====================
__device__ __nv_bfloat16 g_rnnhi[BB * H2], g_rnnlo[BB * H2];
__device__ __nv_bfloat16 g_hid0hi[BB * HH], g_hid0lo[BB * HH];
__device__ __nv_bfloat16 g_hid1hi[BB * HH], g_hid1lo[BB * HH];
__device__ __nv_bfloat16 g_h0hi[BB * HH], g_h0lo[BB * HH];
__device__ __nv_bfloat16 g_cathi[BB * H2], g_catlo[BB * H2];
__device__ float g_h1[BB * HH];
__device__ float g_A[NS * BB * H3];
__device__ float g_Bm[NS * BB * H3];
__device__ float g_B2[NS * BB * H3];
__device__ float g_logits[4 * BB * VV];
__device__ float g_qp[NQ * HH * BB];
__device__ float g_qT[BB * HH];
__device__ float g_scores[BB * SS];
__device__ float g_ctx_part[NCH * BB * HH];
__device__ float g_ctx2[4 * BB * HH];
__device__ float g_ml[BB * NCH * 2];
__device__ float g_red2[BB * 2];
__device__ float g_vred[BB * 2];

// ==================== prep ====================
__global__ void prep_kernel(const int* __restrict__ ids, const float* __restrict__ emb,
                            const float* __restrict__ lctx, const float* __restrict__ hid)
{
    int idx = blockIdx.x * 256 + threadIdx.x;
    if (idx < BB * H2) {
        int b = idx >> 11, k = idx & 2047;
        float v = (k < HH) ? emb[(size_t)ids[b] * HH + k] : lctx[(size_t)b * HH + (k - HH)];
        split1(v, g_rnnhi[idx], g_rnnlo[idx]);
    } else if (idx < BB * H2 + BB * HH) {
        int j = idx - BB * H2;
        split1(hid[j], g_hid0hi[j], g_hid0lo[j]);
    } else {
        int j = idx - BB * H2 - BB * HH;
        split1(hid[BB * HH + j], g_hid1hi[j], g_hid1lo[j]);
    }
}

// ==================== HMMA GEMM body ====================
struct GP {
    const float* W; int ldw;
    const __nv_bfloat16 *Xh, *Xl; int ldx;
    const float* bias;
    float* out; int ldo; size_t pstride; int nch;
};

__device__ __forceinline__ void gemm_body(const GP& p, int bx, int by, char* sm)
{
    __nv_bfloat16* sWh = reinterpret_cast<__nv_bfloat16*>(sm);
    __nv_bfloat16* sWl = reinterpret_cast<__nv_bfloat16*>(sm + 18432);
    __nv_bfloat16* sXh = reinterpret_cast<__nv_bfloat16*>(sm + 36864);
    __nv_bfloat16* sXl = reinterpret_cast<__nv_bfloat16*>(sm + 41472);
    const int tid = threadIdx.x, warp = tid >> 5, lane = tid & 31;
    const int g = lane >> 2, t = lane & 3;
    const int row0 = bx * 128;
    const int kbase = by * p.nch * 64;
    float acc[4][4] = {};
    float4 wr[8];
    uint2 xh[2], xl[2];

    #pragma unroll
    for (int i = 0; i < 8; i++) {
        int e = tid + i * 256, r = e >> 4, c4 = e & 15;
        wr[i] = *reinterpret_cast<const float4*>(p.W + (size_t)(row0 + r) * p.ldw + kbase + c4 * 4);
    }
    #pragma unroll
    for (int i = 0; i < 2; i++) {
        int e = tid + i * 256, r = e >> 4, c4 = e & 15;
        size_t off = (size_t)r * p.ldx + kbase + c4 * 4;
        xh[i] = *reinterpret_cast<const uint2*>(p.Xh + off);
        xl[i] = *reinterpret_cast<const uint2*>(p.Xl + off);
    }

    for (int c = 0; c < p.nch; c++) {
        __syncthreads();
        #pragma unroll
        for (int i = 0; i < 8; i++) {
            int e = tid + i * 256, r = e >> 4, c4 = e & 15;
            uint32_t h0, l0, h1, l1;
            split_pack(wr[i].x, wr[i].y, h0, l0);
            split_pack(wr[i].z, wr[i].w, h1, l1);
            *reinterpret_cast<uint2*>(&sWh[r * 72 + c4 * 4]) = make_uint2(h0, h1);
            *reinterpret_cast<uint2*>(&sWl[r * 72 + c4 * 4]) = make_uint2(l0, l1);
        }
        #pragma unroll
        for (int i = 0; i < 2; i++) {
            int e = tid + i * 256, r = e >> 4, c4 = e & 15;
            *reinterpret_cast<uint2*>(&sXh[r * 72 + c4 * 4]) = xh[i];
            *reinterpret_cast<uint2*>(&sXl[r * 72 + c4 * 4]) = xl[i];
        }
        __syncthreads();
        if (c + 1 < p.nch) {
            const int kb = kbase + (c + 1) * 64;
            #pragma unroll
            for (int i = 0; i < 8; i++) {
                int e = tid + i * 256, r = e >> 4, c4 = e & 15;
                wr[i] = *reinterpret_cast<const float4*>(p.W + (size_t)(row0 + r) * p.ldw + kb + c4 * 4);
            }
            #pragma unroll
            for (int i = 0; i < 2; i++) {
                int e = tid + i * 256, r = e >> 4, c4 = e & 15;
                size_t off = (size_t)r * p.ldx + kb + c4 * 4;
                xh[i] = *reinterpret_cast<const uint2*>(p.Xh + off);
                xl[i] = *reinterpret_cast<const uint2*>(p.Xl + off);
            }
        }
        #pragma unroll
        for (int ks = 0; ks < 4; ks++) {
            const int ko = ks * 16;
            const int ra = (warp * 16 + g) * 72 + ko + t * 2;
            uint32_t ah[4], al[4];
            ah[0] = *reinterpret_cast<const uint32_t*>(&sWh[ra]);
            ah[1] = *reinterpret_cast<const uint32_t*>(&sWh[ra + 8 * 72]);
            ah[2] = *reinterpret_cast<const uint32_t*>(&sWh[ra + 8]);
            ah[3] = *reinterpret_cast<const uint32_t*>(&sWh[ra + 8 * 72 + 8]);
            al[0] = *reinterpret_cast<const uint32_t*>(&sWl[ra]);
            al[1] = *reinterpret_cast<const uint32_t*>(&sWl[ra + 8 * 72]);
            al[2] = *reinterpret_cast<const uint32_t*>(&sWl[ra + 8]);
            al[3] = *reinterpret_cast<const uint32_t*>(&sWl[ra + 8 * 72 + 8]);
            #pragma unroll
            for (int nt = 0; nt < 4; nt++) {
                const int rb = (nt * 8 + g) * 72 + ko + t * 2;
                uint32_t bh[2], bl[2];
                bh[0] = *reinterpret_cast<const uint32_t*>(&sXh[rb]);
                bh[1] = *reinterpret_cast<const uint32_t*>(&sXh[rb + 8]);
                bl[0] = *reinterpret_cast<const uint32_t*>(&sXl[rb]);
                bl[1] = *reinterpret_cast<const uint32_t*>(&sXl[rb + 8]);
                mma16816(acc[nt], ah, bh);
                mma16816(acc[nt], ah, bl);
                mma16816(acc[nt], al, bh);
            }
        }
    }
    __syncthreads();
    float* T = reinterpret_cast<float*>(sWh);
    #pragma unroll
    for (int nt = 0; nt < 4; nt++) {
        int b0 = nt * 8 + t * 2;
        int j0 = warp * 16 + g;
        T[b0 * 132 + j0]           = acc[nt][0];
        T[(b0 + 1) * 132 + j0]     = acc[nt][1];
        T[b0 * 132 + j0 + 8]       = acc[nt][2];
        T[(b0 + 1) * 132 + j0 + 8] = acc[nt][3];
    }
    __syncthreads();
    float* outp = p.out + (size_t)by * p.pstride;
    const float* bias = p.bias;
    #pragma unroll
    for (int i = 0; i < 4; i++) {
        int b = (tid >> 5) + i * 8;
        int j = lane * 4;
        float4 v = *reinterpret_cast<const float4*>(&T[b * 132 + j]);
        if (bias && by == 0) {
            v.x += bias[row0 + j];
            v.y += bias[row0 + j + 1];
            v.z += bias[row0 + j + 2];
            v.w += bias[row0 + j + 3];
        }
        *reinterpret_cast<float4*>(&outp[(size_t)b * p.ldo + row0 + j]) = v;
    }
}

// standalone GEMM: up to 3 configs via blockIdx.z
__global__ void __launch_bounds__(256, 2)
mma_gemm_kernel(GP p0, GP p1, GP p2)
{
    __shared__ alignas(16) char sm[GSMEM];
    const GP& p = (blockIdx.z == 0) ? p0 : (blockIdx.z == 1 ? p1 : p2);
    gemm_body(p, blockIdx.x, blockIdx.y, sm);
}

// ==================== MEGA: logits h1-half GEMM CTAs + attention CTAs ====================
#define NLGB (250 * NLG)
__global__ void __launch_bounds__(256)
attn_mega_kernel(GP lg, const float* __restrict__ enc)
{
    extern __shared__ char dsm[];
    if (blockIdx.x < NLGB) {
        gemm_body(lg, blockIdx.x % 250, blockIdx.x / 250, dsm);
        return;
    }
    float* tile = reinterpret_cast<float*>(dsm);
    float* qs   = tile + ACH * HH;
    float* sc   = qs + HH;
    const int bx = blockIdx.x - NLGB;
    const int sp = bx & (NCH - 1), b = bx >> 7;
    const int tid = threadIdx.x, warp = tid >> 5, lane = tid & 31;
    *reinterpret_cast<float4*>(&qs[tid * 4]) =
        *reinterpret_cast<const float4*>(&g_qT[(size_t)b * HH + tid * 4]);
    __syncthreads();
    for (int s = warp; s < ACH; s += 8) {
        const float4* ep = reinterpret_cast<const float4*>(
            enc + ((size_t)b * SS + (size_t)sp * ACH + s) * HH);
        float acc = 0.f;
        #pragma unroll
        for (int j = 0; j < 8; j++) {
            float4 ev = ep[lane + 32 * j];
            float4 qv = *reinterpret_cast<const float4*>(&qs[(lane + 32 * j) * 4]);
            *reinterpret_cast<float4*>(&tile[s * HH + (lane + 32 * j) * 4]) = ev;
            acc = fmaf(ev.x, qv.x, fmaf(ev.y, qv.y, fmaf(ev.z, qv.z, fmaf(ev.w, qv.w, acc))));
        }
        #pragma unroll
        for (int o = 16; o; o >>= 1) acc += __shfl_xor_sync(0xffffffffu, acc, o);
        if (lane == 0) {
            sc[s] = acc;
            g_scores[(size_t)b * SS + sp * ACH + s] = acc;
        }
    }
    __syncthreads();
    float m = sc[0];
    #pragma unroll
    for (int s = 1; s < ACH; s++) m = fmaxf(m, sc[s]);
    float l = 0.f;
    float4 ctx = {0.f, 0.f, 0.f, 0.f};
    #pragma unroll
    for (int s = 0; s < ACH; s++) {
        float w = __expf(sc[s] - m);
        l += w;
        float4 ev = *reinterpret_cast<const float4*>(&tile[s * HH + tid * 4]);
        ctx.x = fmaf(w, ev.x, ctx.x);
        ctx.y = fmaf(w, ev.y, ctx.y);
        ctx.z = fmaf(w, ev.z, ctx.z);
        ctx.w = fmaf(w, ev.w, ctx.w);
    }
    *reinterpret_cast<float4*>(&g_ctx_part[((size_t)sp * BB + b) * HH + tid * 4]) = ctx;
    if (tid == 0) {
        g_ml[(b * NCH + sp) * 2] = m;
        g_ml[(b * NCH + sp) * 2 + 1] = l;
    }
}

// ==================== FFMA2 GEMM, W reduction-major (q = h1 @ W_attn) ====================
__global__ void __launch_bounds__(256)
gemmT_kernel(const float* __restrict__ X, int ldx,
             const float* __restrict__ Wm, int M,
             float* __restrict__ out, int n_chunks)
{
    __shared__ float Ws[64 * 68];
    __shared__ float Xs[32 * 68];
    const int tid = threadIdx.x, warp = tid >> 5, lane = tid & 31;
    const int row0 = blockIdx.x * 64;
    const int kbase = blockIdx.y * n_chunks * 64;
    unsigned long long acc2[8] = {0, 0, 0, 0, 0, 0, 0, 0};

    for (int c = 0; c < n_chunks; c++) {
        const int k0 = kbase + c * 64;
        __syncthreads();
        #pragma unroll
        for (int i = 0; i < 4; i++) {
            int e = tid + i * 256, r4 = e & 15, kk = e >> 4;
            float4 w = *reinterpret_cast<const float4*>(Wm + (size_t)(k0 + kk) * M + row0 + r4 * 4);
            Ws[(r4 * 4 + 0) * 68 + kk] = w.x;
            Ws[(r4 * 4 + 1) * 68 + kk] = w.y;
            Ws[(r4 * 4 + 2) * 68 + kk] = w.z;
            Ws[(r4 * 4 + 3) * 68 + kk] = w.w;
        }
        #pragma unroll
        for (int i = 0; i < 2; i++) {
            int e = tid + i * 256, b = e >> 4, kk4 = e & 15;
            float4 v = *(reinterpret_cast<const float4*>(X + (size_t)b * ldx + k0) + kk4);
            *reinterpret_cast<float4*>(&Xs[b * 68 + kk4 * 4]) = v;
        }
        __syncthreads();
        #pragma unroll
        for (int kk = 0; kk < 16; kk++) {
            ulonglong2 c01 = *reinterpret_cast<const ulonglong2*>(&Xs[lane * 68 + kk * 4]);
            #pragma unroll
            for (int r = 0; r < 8; r++) {
                ulonglong2 w = *reinterpret_cast<const ulonglong2*>(&Ws[(warp * 8 + r) * 68 + kk * 4]);
                FMA2(acc2[r], w.x, c01.x);
                FMA2(acc2[r], w.y, c01.y);
            }
        }
    }
    float* op = out + (size_t)blockIdx.y * HH * BB;
    #pragma unroll
    for (int r = 0; r < 8; r++) {
        float v = __uint_as_float((unsigned)acc2[r]) + __uint_as_float((unsigned)(acc2[r] >> 32));
        op[(size_t)(row0 + warp * 8 + r) * BB + lane] = v;
    }
}

// ==================== GRU gate ====================
__global__ void gru_gate_kernel(const float* __restrict__ A, const float* __restrict__ Bm,
                                const float* __restrict__ bih, const float* __restrict__ bhh,
                                const float* __restrict__ hprev,
                                float* __restrict__ out_hidden,
                                float* __restrict__ h_fp32,
                                __nv_bfloat16* __restrict__ hi_dst,
                                __nv_bfloat16* __restrict__ lo_dst, int xstride)
{
    int idx = blockIdx.x * 256 + threadIdx.x;
    int b = idx >> 10, i = idx & 1023;
    float ir = bih[i], iz = bih[HH + i], in_ = bih[2 * HH + i];
    float hr = bhh[i], hz = bhh[HH + i], hn = bhh[2 * HH + i];
    #pragma unroll
    for (int p = 0; p < NS; p++) {
        size_t base = (size_t)p * BB * H3 + (size_t)b * H3;
        ir  += A[base + i];
        iz  += A[base + HH + i];
        in_ += A[base + 2 * HH + i];
        hr  += Bm[base + i];
        hz  += Bm[base + HH + i];
        hn  += Bm[base + 2 * HH + i];
    }
    float r = 1.f / (1.f + expf(-(ir + hr)));
    float z = 1.f / (1.f + expf(-(iz + hz)));
    float n = tanhf(in_ + r * hn);
    float h = (1.f - z) * n + z * hprev[(size_t)b * HH + i];
    out_hidden[(size_t)b * HH + i] = h;
    if (h_fp32) h_fp32[(size_t)b * HH + i] = h;
    __nv_bfloat16 hi, lo;
    split1(h, hi, lo);
    hi_dst[(size_t)b * xstride + i] = hi;
    lo_dst[(size_t)b * xstride + i] = lo;
}

// ==================== q: sum NQ partials, transpose -> [b][j] ====================
__global__ void qfix_kernel()
{
    int idx = blockIdx.x * 256 + threadIdx.x;
    int b = idx >> 10, j = idx & 1023;
    float v = 0.f;
    #pragma unroll
    for (int p = 0; p < NQ; p++) v += g_qp[(size_t)p * HH * BB + (size_t)j * BB + b];
    g_qT[idx] = v;
}

// ==================== combine B (with inlined softmax stats) + C ====================
__global__ void __launch_bounds__(256)
combine_b_kernel()
{
    __shared__ float wsh[NCH];
    __shared__ float red[8];
    const int z = blockIdx.x, b = blockIdx.y, tid = threadIdx.x;
    const int lane = tid & 31, warp = tid >> 5;
    float mc = (tid < NCH) ? g_ml[(b * NCH + tid) * 2] : -1e30f;
    float m = mc;
    #pragma unroll
    for (int o = 16; o; o >>= 1) m = fmaxf(m, __shfl_xor_sync(0xffffffffu, m, o));
    if (!lane) red[warp] = m;
    __syncthreads();
    float M0 = red[0];
    #pragma unroll
    for (int i = 1; i < 8; i++) M0 = fmaxf(M0, red[i]);
    __syncthreads();
    float w = __expf(mc - M0);
    float ls = 0.f;
    if (tid < NCH) {
        wsh[tid] = w;
        ls = w * g_ml[(b * NCH + tid) * 2 + 1];
    }
    #pragma unroll
    for (int o = 16; o; o >>= 1) ls += __shfl_xor_sync(0xffffffffu, ls, o);
    if (!lane) red[warp] = ls;
    __syncthreads();
    if (z == 0 && tid == 0) {
        float L = 0.f;
        #pragma unroll
        for (int i = 0; i < 8; i++) L += red[i];
        g_red2[2 * b] = M0;
        g_red2[2 * b + 1] = 1.f / L;
    }
    float4 acc = {0.f, 0.f, 0.f, 0.f};
    #pragma unroll 4
    for (int c = 0; c < 32; c++) {
        float wc = wsh[z * 32 + c];
        float4 p = *reinterpret_cast<const float4*>(
            &g_ctx_part[((size_t)(z * 32 + c) * BB + b) * HH + tid * 4]);
        acc.x = fmaf(wc, p.x, acc.x);
        acc.y = fmaf(wc, p.y, acc.y);
        acc.z = fmaf(wc, p.z, acc.z);
        acc.w = fmaf(wc, p.w, acc.w);
    }
    *reinterpret_cast<float4*>(&g_ctx2[((size_t)z * BB + b) * HH + tid * 4]) = acc;
}

__global__ void __launch_bounds__(256)
combine_c_kernel(float* __restrict__ out_ctx)
{
    const int b = blockIdx.x, tid = threadIdx.x;
    float invL = g_red2[2 * b + 1];
    float4 acc = {0.f, 0.f, 0.f, 0.f};
    #pragma unroll
    for (int z = 0; z < 4; z++) {
        float4 p = *reinterpret_cast<const float4*>(&g_ctx2[((size_t)z * BB + b) * HH + tid * 4]);
        acc.x += p.x; acc.y += p.y; acc.z += p.z; acc.w += p.w;
    }
    acc.x *= invL; acc.y *= invL; acc.z *= invL; acc.w *= invL;
    *reinterpret_cast<float4*>(&out_ctx[(size_t)b * HH + tid * 4]) = acc;
    size_t cb = (size_t)b * H2 + HH + tid * 4;
    float vv[4] = {acc.x, acc.y, acc.z, acc.w};
    #pragma unroll
    for (int k = 0; k < 4; k++) split1(vv[k], g_cathi[cb + k], g_catlo[cb + k]);
}

// ==================== vocab softmax reduce + finalize ====================
__global__ void vocab_reduce_kernel()
{
    __shared__ float red[8];
    int b = blockIdx.x, tid = threadIdx.x, lane = tid & 31, warp = tid >> 5;
    float m = -1e30f;
    for (int v = tid; v < VV; v += 256) {
        float lg = 0.f;
        #pragma unroll
        for (int p = 0; p < 4; p++) lg += g_logits[(size_t)p * BB * VV + (size_t)b * VV + v];
        m = fmaxf(m, lg);
    }
    #pragma unroll
    for (int o = 16; o; o >>= 1) m = fmaxf(m, __shfl_xor_sync(0xffffffffu, m, o));
    if (!lane) red[warp] = m;
    __syncthreads();
    float M0 = red[0];
    #pragma unroll
    for (int i = 1; i < 8; i++) M0 = fmaxf(M0, red[i]);
    __syncthreads();
    float s = 0.f;
    for (int v = tid; v < VV; v += 256) {
        float lg = 0.f;
        #pragma unroll
        for (int p = 0; p < 4; p++) lg += g_logits[(size_t)p * BB * VV + (size_t)b * VV + v];
        s += __expf(lg - M0);
    }
    #pragma unroll
    for (int o = 16; o; o >>= 1) s += __shfl_xor_sync(0xffffffffu, s, o);
    if (!lane) red[warp] = s;
    __syncthreads();
    if (tid == 0) {
        float t = 0.f;
        #pragma unroll
        for (int i = 0; i < 8; i++) t += red[i];
        g_vred[2 * b] = M0;
        g_vred[2 * b + 1] = 1.f / t;
    }
}

__global__ void finalize_kernel(float* __restrict__ out_output, float* __restrict__ out_attn)
{
    int idx = blockIdx.x * 256 + threadIdx.x;
    if (idx < BB * VV) {
        int b = idx / VV;
        float lg = 0.f;
        #pragma unroll
        for (int p = 0; p < 4; p++) lg += g_logits[(size_t)p * BB * VV + idx];
        out_output[idx] = __expf(lg - g_vred[2 * b]) * g_vred[2 * b + 1];
    } else {
        int j = idx - BB * VV;
        int b = j >> 11;
        out_attn[j] = __expf(g_scores[j] - g_red2[2 * b]) * g_red2[2 * b + 1];
    }
}

// ==================== launch ====================
extern "C" void kernel_launch(void* const* d_in, const int* in_sizes, int n_in,
                              void* d_out, int out_size)
{
    const int*   ids  = (const int*)  d_in[0];
    const float* lctx = (const float*)d_in[1];
    const float* hid  = (const float*)d_in[2];
    const float* enc  = (const float*)d_in[3];
    const float* emb  = (const float*)d_in[4];
    const float* Wat  = (const float*)d_in[5];
    // d_in[6] b_attn: per-batch-constant score shift, softmax-invariant -> dropped
    const float* Wih0 = (const float*)d_in[7];
    const float* Whh0 = (const float*)d_in[8];
    const float* bih0 = (const float*)d_in[9];
    const float* bhh0 = (const float*)d_in[10];
    const float* Wih1 = (const float*)d_in[11];
    const float* Whh1 = (const float*)d_in[12];
    const float* bih1 = (const float*)d_in[13];
    const float* bhh1 = (const float*)d_in[14];
    const float* Wout = (const float*)d_in[15];
    const float* bout = (const float*)d_in[16];

    float* out        = (float*)d_out;
    float* out_output = out;
    float* out_ctx    = out + (size_t)BB * VV;
    float* out_hidden = out_ctx + (size_t)BB * HH;
    float* out_attn   = out_hidden + (size_t)2 * BB * HH;

    float *pA, *pB, *pB2, *pH1, *pQp, *pLog;
    __nv_bfloat16 *pRh, *pRl, *pH0h, *pH0l, *pD0h, *pD0l, *pD1h, *pD1l, *pCh, *pCl;
    cudaGetSymbolAddress((void**)&pA,   g_A);
    cudaGetSymbolAddress((void**)&pB,   g_Bm);
    cudaGetSymbolAddress((void**)&pB2,  g_B2);
    cudaGetSymbolAddress((void**)&pH1,  g_h1);
    cudaGetSymbolAddress((void**)&pQp,  g_qp);
    cudaGetSymbolAddress((void**)&pLog, g_logits);
    cudaGetSymbolAddress((void**)&pRh,  g_rnnhi);
    cudaGetSymbolAddress((void**)&pRl,  g_rnnlo);
    cudaGetSymbolAddress((void**)&pH0h, g_h0hi);
    cudaGetSymbolAddress((void**)&pH0l, g_h0lo);
    cudaGetSymbolAddress((void**)&pD0h, g_hid0hi);
    cudaGetSymbolAddress((void**)&pD0l, g_hid0lo);
    cudaGetSymbolAddress((void**)&pD1h, g_hid1hi);
    cudaGetSymbolAddress((void**)&pD1l, g_hid1lo);
    cudaGetSymbolAddress((void**)&pCh,  g_cathi);
    cudaGetSymbolAddress((void**)&pCl,  g_catlo);

    cudaFuncSetAttribute(attn_mega_kernel, cudaFuncAttributeMaxDynamicSharedMemorySize, ASMEM);

    const size_t PSTR = (size_t)BB * H3;

    prep_kernel<<<512, 256>>>(ids, emb, lctx, hid);
    // GRU layer 0 + early Whh1 (all input-independent GEMMs in one launch, grid.z=3)
    {
        GP a = {Wih0, H2, pRh, pRl, H2, nullptr, pA, H3, PSTR, 4};
        GP b = {Whh0, HH, pD0h, pD0l, HH, nullptr, pB, H3, PSTR, 2};
        GP c = {Whh1, HH, pD1h, pD1l, HH, nullptr, pB2, H3, PSTR, 2};
        mma_gemm_kernel<<<dim3(24, NS, 3), 256>>>(a, b, c);
    }
    gru_gate_kernel<<<128, 256>>>(pA, pB, bih0, bhh0, hid, out_hidden,
                                  nullptr, pH0h, pH0l, HH);
    // GRU layer 1: only Wih1 (Whh1 partials already in g_B2)
    {
        GP a = {Wih1, HH, pH0h, pH0l, HH, nullptr, pA, H3, PSTR, 2};
        mma_gemm_kernel<<<dim3(24, NS, 1), 256>>>(a, a, a);
    }
    gru_gate_kernel<<<128, 256>>>(pA, pB2, bih1, bhh1, hid + (size_t)BB * HH,
                                  out_hidden + (size_t)BB * HH, pH1, pCh, pCl, H2);
    // q = h1 @ W_attn (K-split NQ=8) -> sum+transpose
    gemmT_kernel<<<dim3(16, NQ), 256>>>(pH1, HH, Wat, HH, pQp, 2);
    qfix_kernel<<<128, 256>>>();
    // MEGA: attention + logits h1-half co-resident
    {
        GP lg = {Wout, H2, pCh, pCl, H2, bout, pLog, VV, (size_t)BB * VV, 8};
        attn_mega_kernel<<<NLGB + NCH * BB, 256, ASMEM>>>(lg, enc);
    }
    combine_b_kernel<<<dim3(4, BB), 256>>>();
    combine_c_kernel<<<BB, 256>>>(out_ctx);
    // logits ctx-half
    {
        GP c = {Wout + HH, H2, pCh + HH, pCl + HH, H2, nullptr,
                pLog + (size_t)2 * BB * VV, VV, (size_t)BB * VV, 8};
        mma_gemm_kernel<<<dim3(250, NLG, 1), 256>>>(c, c, c);
    }
    vocab_reduce_kernel<<<BB, 256>>>();
    finalize_kernel<<<(BB * VV + BB * SS) / 256, 256>>>(out_output, out_attn);
}

// round 15
// speedup vs baseline: 1.0743x; 1.0743x over previous
#include <cuda_runtime.h>
#include <cuda_bf16.h>
#include <cstdint>

#define BB 32
#define HH 1024
#define SS 2048
#define VV 32000
#define H3 3072
#define H2 2048
#define ACH 16
#define NCH (SS/ACH)          // 128
#define NS 8                  // K-split partials for GRU GEMMs
#define NQ 8                  // K-split for q GEMM
#define NLG 2                 // K-split per logits half
#define ASMEM ((ACH*HH + HH + ACH) * 4)   // attn tile + q + sc
#define GSMEM 46080                        // gemm staging bytes

#define FMA2(acc, a, b) asm("fma.rn.f32x2 %0, %1, %2, %0;" : "+l"(acc) : "l"(a), "l"(b))

__device__ __forceinline__ void mma16816(float* d, const uint32_t* a, const uint32_t* b) {
    asm volatile("mma.sync.aligned.m16n8k16.row.col.f32.bf16.bf16.f32 "
                 "{%0,%1,%2,%3}, {%4,%5,%6,%7}, {%8,%9}, {%0,%1,%2,%3};"
                 : "+f"(d[0]), "+f"(d[1]), "+f"(d[2]), "+f"(d[3])
                 : "r"(a[0]), "r"(a[1]), "r"(a[2]), "r"(a[3]), "r"(b[0]), "r"(b[1]));
}

__device__ __forceinline__ void split1(float x, __nv_bfloat16& hi, __nv_bfloat16& lo) {
    hi = __float2bfloat16(x);
    lo = __float2bfloat16(x - __bfloat162float(hi));
}
__device__ __forceinline__ void split_pack(float a, float b, uint32_t& hi, uint32_t& lo) {
    __nv_bfloat162 h = __floats2bfloat162_rn(a, b);
    __nv_bfloat162 l2 = __floats2bfloat162_rn(a - __bfloat162float(h.x), b - __bfloat162float(h.y));
    hi = *reinterpret_cast<uint32_t*>(&h);
    lo = *reinterpret_cast<uint32_t*>(&l2);
}

// ==================== scratch ====================
__device__ __nv_bfloat16 g_rnnhi[BB * H2], g_rnnlo[BB * H2];
__device__ __nv_bfloat16 g_hid0hi[BB * HH], g_hid0lo[BB * HH];
__device__ __nv_bfloat16 g_hid1hi[BB * HH], g_hid1lo[BB * HH];
__device__ __nv_bfloat16 g_h0hi[BB * HH], g_h0lo[BB * HH];
__device__ __nv_bfloat16 g_cathi[BB * H2], g_catlo[BB * H2];
__device__ float g_h1[BB * HH];
__device__ float g_A[NS * BB * H3];
__device__ float g_Bm[NS * BB * H3];
__device__ float g_logits[4 * BB * VV];
__device__ float g_qp[NQ * HH * BB];
__device__ float g_qT[BB * HH];
__device__ float g_scores[BB * SS];
__device__ float g_ctx_part[NCH * BB * HH];
__device__ float g_ctx2[4 * BB * HH];
__device__ float g_wc[BB * NCH];
__device__ float g_ml[BB * NCH * 2];
__device__ float g_red2[BB * 2];
__device__ float g_vred[BB * 2];

// ==================== prep ====================
__global__ void prep_kernel(const int* __restrict__ ids, const float* __restrict__ emb,
                            const float* __restrict__ lctx, const float* __restrict__ hid)
{
    int idx = blockIdx.x * 256 + threadIdx.x;
    if (idx < BB * H2) {
        int b = idx >> 11, k = idx & 2047;
        float v = (k < HH) ? emb[(size_t)ids[b] * HH + k] : lctx[(size_t)b * HH + (k - HH)];
        split1(v, g_rnnhi[idx], g_rnnlo[idx]);
    } else if (idx < BB * H2 + BB * HH) {
        int j = idx - BB * H2;
        split1(hid[j], g_hid0hi[j], g_hid0lo[j]);
    } else {
        int j = idx - BB * H2 - BB * HH;
        split1(hid[BB * HH + j], g_hid1hi[j], g_hid1lo[j]);
    }
}

// ==================== HMMA GEMM body ====================
struct GP {
    const float* W; int ldw;
    const __nv_bfloat16 *Xh, *Xl; int ldx;
    const float* bias;
    float* out; int ldo; size_t pstride; int nch;
};

__device__ __forceinline__ void gemm_body(const GP& p, int bx, int by, char* sm)
{
    __nv_bfloat16* sWh = reinterpret_cast<__nv_bfloat16*>(sm);
    __nv_bfloat16* sWl = reinterpret_cast<__nv_bfloat16*>(sm + 18432);
    __nv_bfloat16* sXh = reinterpret_cast<__nv_bfloat16*>(sm + 36864);
    __nv_bfloat16* sXl = reinterpret_cast<__nv_bfloat16*>(sm + 41472);
    const int tid = threadIdx.x, warp = tid >> 5, lane = tid & 31;
    const int g = lane >> 2, t = lane & 3;
    const int row0 = bx * 128;
    const int kbase = by * p.nch * 64;
    float acc[4][4] = {};
    float4 wr[8];
    uint2 xh[2], xl[2];

    #pragma unroll
    for (int i = 0; i < 8; i++) {
        int e = tid + i * 256, r = e >> 4, c4 = e & 15;
        wr[i] = *reinterpret_cast<const float4*>(p.W + (size_t)(row0 + r) * p.ldw + kbase + c4 * 4);
    }
    #pragma unroll
    for (int i = 0; i < 2; i++) {
        int e = tid + i * 256, r = e >> 4, c4 = e & 15;
        size_t off = (size_t)r * p.ldx + kbase + c4 * 4;
        xh[i] = *reinterpret_cast<const uint2*>(p.Xh + off);
        xl[i] = *reinterpret_cast<const uint2*>(p.Xl + off);
    }

    for (int c = 0; c < p.nch; c++) {
        __syncthreads();
        #pragma unroll
        for (int i = 0; i < 8; i++) {
            int e = tid + i * 256, r = e >> 4, c4 = e & 15;
            uint32_t h0, l0, h1, l1;
            split_pack(wr[i].x, wr[i].y, h0, l0);
            split_pack(wr[i].z, wr[i].w, h1, l1);
            *reinterpret_cast<uint2*>(&sWh[r * 72 + c4 * 4]) = make_uint2(h0, h1);
            *reinterpret_cast<uint2*>(&sWl[r * 72 + c4 * 4]) = make_uint2(l0, l1);
        }
        #pragma unroll
        for (int i = 0; i < 2; i++) {
            int e = tid + i * 256, r = e >> 4, c4 = e & 15;
            *reinterpret_cast<uint2*>(&sXh[r * 72 + c4 * 4]) = xh[i];
            *reinterpret_cast<uint2*>(&sXl[r * 72 + c4 * 4]) = xl[i];
        }
        __syncthreads();
        if (c + 1 < p.nch) {
            const int kb = kbase + (c + 1) * 64;
            #pragma unroll
            for (int i = 0; i < 8; i++) {
                int e = tid + i * 256, r = e >> 4, c4 = e & 15;
                wr[i] = *reinterpret_cast<const float4*>(p.W + (size_t)(row0 + r) * p.ldw + kb + c4 * 4);
            }
            #pragma unroll
            for (int i = 0; i < 2; i++) {
                int e = tid + i * 256, r = e >> 4, c4 = e & 15;
                size_t off = (size_t)r * p.ldx + kb + c4 * 4;
                xh[i] = *reinterpret_cast<const uint2*>(p.Xh + off);
                xl[i] = *reinterpret_cast<const uint2*>(p.Xl + off);
            }
        }
        #pragma unroll
        for (int ks = 0; ks < 4; ks++) {
            const int ko = ks * 16;
            const int ra = (warp * 16 + g) * 72 + ko + t * 2;
            uint32_t ah[4], al[4];
            ah[0] = *reinterpret_cast<const uint32_t*>(&sWh[ra]);
            ah[1] = *reinterpret_cast<const uint32_t*>(&sWh[ra + 8 * 72]);
            ah[2] = *reinterpret_cast<const uint32_t*>(&sWh[ra + 8]);
            ah[3] = *reinterpret_cast<const uint32_t*>(&sWh[ra + 8 * 72 + 8]);
            al[0] = *reinterpret_cast<const uint32_t*>(&sWl[ra]);
            al[1] = *reinterpret_cast<const uint32_t*>(&sWl[ra + 8 * 72]);
            al[2] = *reinterpret_cast<const uint32_t*>(&sWl[ra + 8]);
            al[3] = *reinterpret_cast<const uint32_t*>(&sWl[ra + 8 * 72 + 8]);
            #pragma unroll
            for (int nt = 0; nt < 4; nt++) {
                const int rb = (nt * 8 + g) * 72 + ko + t * 2;
                uint32_t bh[2], bl[2];
                bh[0] = *reinterpret_cast<const uint32_t*>(&sXh[rb]);
                bh[1] = *reinterpret_cast<const uint32_t*>(&sXh[rb + 8]);
                bl[0] = *reinterpret_cast<const uint32_t*>(&sXl[rb]);
                bl[1] = *reinterpret_cast<const uint32_t*>(&sXl[rb + 8]);
                mma16816(acc[nt], ah, bh);
                mma16816(acc[nt], ah, bl);
                mma16816(acc[nt], al, bh);
            }
        }
    }
    __syncthreads();
    float* T = reinterpret_cast<float*>(sWh);
    #pragma unroll
    for (int nt = 0; nt < 4; nt++) {
        int b0 = nt * 8 + t * 2;
        int j0 = warp * 16 + g;
        T[b0 * 132 + j0]           = acc[nt][0];
        T[(b0 + 1) * 132 + j0]     = acc[nt][1];
        T[b0 * 132 + j0 + 8]       = acc[nt][2];
        T[(b0 + 1) * 132 + j0 + 8] = acc[nt][3];
    }
    __syncthreads();
    float* outp = p.out + (size_t)by * p.pstride;
    const float* bias = p.bias;
    #pragma unroll
    for (int i = 0; i < 4; i++) {
        int b = (tid >> 5) + i * 8;
        int j = lane * 4;
        float4 v = *reinterpret_cast<const float4*>(&T[b * 132 + j]);
        if (bias && by == 0) {
            v.x += bias[row0 + j];
            v.y += bias[row0 + j + 1];
            v.z += bias[row0 + j + 2];
            v.w += bias[row0 + j + 3];
        }
        *reinterpret_cast<float4*>(&outp[(size_t)b * p.ldo + row0 + j]) = v;
    }
}

// standalone GEMM kernel (GRU pairs + logits ctx-half)
__global__ void __launch_bounds__(256, 2)
mma_gemm_kernel(GP p0, GP p1)
{
    __shared__ alignas(16) char sm[GSMEM];
    const GP& p = blockIdx.z ? p1 : p0;
    gemm_body(p, blockIdx.x, blockIdx.y, sm);
}

// ==================== MEGA: logits h1-half GEMM CTAs + attention CTAs ====================
#define NLGB (250 * NLG)     // 500 gemm blocks
__global__ void __launch_bounds__(256)
attn_mega_kernel(GP lg, const float* __restrict__ enc)
{
    extern __shared__ char dsm[];
    if (blockIdx.x < NLGB) {
        gemm_body(lg, blockIdx.x % 250, blockIdx.x / 250, dsm);
        return;
    }
    float* tile = reinterpret_cast<float*>(dsm);
    float* qs   = tile + ACH * HH;
    float* sc   = qs + HH;
    const int bx = blockIdx.x - NLGB;
    const int sp = bx & (NCH - 1), b = bx >> 7;
    const int tid = threadIdx.x, warp = tid >> 5, lane = tid & 31;
    *reinterpret_cast<float4*>(&qs[tid * 4]) =
        *reinterpret_cast<const float4*>(&g_qT[(size_t)b * HH + tid * 4]);
    __syncthreads();
    for (int s = warp; s < ACH; s += 8) {
        const float4* ep = reinterpret_cast<const float4*>(
            enc + ((size_t)b * SS + (size_t)sp * ACH + s) * HH);
        float acc = 0.f;
        #pragma unroll
        for (int j = 0; j < 8; j++) {
            float4 ev = ep[lane + 32 * j];
            float4 qv = *reinterpret_cast<const float4*>(&qs[(lane + 32 * j) * 4]);
            *reinterpret_cast<float4*>(&tile[s * HH + (lane + 32 * j) * 4]) = ev;
            acc = fmaf(ev.x, qv.x, fmaf(ev.y, qv.y, fmaf(ev.z, qv.z, fmaf(ev.w, qv.w, acc))));
        }
        #pragma unroll
        for (int o = 16; o; o >>= 1) acc += __shfl_xor_sync(0xffffffffu, acc, o);
        if (lane == 0) {
            sc[s] = acc;
            g_scores[(size_t)b * SS + sp * ACH + s] = acc;
        }
    }
    __syncthreads();
    float m = sc[0];
    #pragma unroll
    for (int s = 1; s < ACH; s++) m = fmaxf(m, sc[s]);
    float l = 0.f;
    float4 ctx = {0.f, 0.f, 0.f, 0.f};
    #pragma unroll
    for (int s = 0; s < ACH; s++) {
        float w = __expf(sc[s] - m);
        l += w;
        float4 ev = *reinterpret_cast<const float4*>(&tile[s * HH + tid * 4]);
        ctx.x = fmaf(w, ev.x, ctx.x);
        ctx.y = fmaf(w, ev.y, ctx.y);
        ctx.z = fmaf(w, ev.z, ctx.z);
        ctx.w = fmaf(w, ev.w, ctx.w);
    }
    *reinterpret_cast<float4*>(&g_ctx_part[((size_t)sp * BB + b) * HH + tid * 4]) = ctx;
    if (tid == 0) {
        g_ml[(b * NCH + sp) * 2] = m;
        g_ml[(b * NCH + sp) * 2 + 1] = l;
    }
}

// ==================== FFMA2 GEMM, W reduction-major (q = h1 @ W_attn) ====================
__global__ void __launch_bounds__(256)
gemmT_kernel(const float* __restrict__ X, int ldx,
             const float* __restrict__ Wm, int M,
             float* __restrict__ out, int n_chunks)
{
    __shared__ float Ws[64 * 68];
    __shared__ float Xs[32 * 68];
    const int tid = threadIdx.x, warp = tid >> 5, lane = tid & 31;
    const int row0 = blockIdx.x * 64;
    const int kbase = blockIdx.y * n_chunks * 64;
    unsigned long long acc2[8] = {0, 0, 0, 0, 0, 0, 0, 0};

    for (int c = 0; c < n_chunks; c++) {
        const int k0 = kbase + c * 64;
        __syncthreads();
        #pragma unroll
        for (int i = 0; i < 4; i++) {
            int e = tid + i * 256, r4 = e & 15, kk = e >> 4;
            float4 w = *reinterpret_cast<const float4*>(Wm + (size_t)(k0 + kk) * M + row0 + r4 * 4);
            Ws[(r4 * 4 + 0) * 68 + kk] = w.x;
            Ws[(r4 * 4 + 1) * 68 + kk] = w.y;
            Ws[(r4 * 4 + 2) * 68 + kk] = w.z;
            Ws[(r4 * 4 + 3) * 68 + kk] = w.w;
        }
        #pragma unroll
        for (int i = 0; i < 2; i++) {
            int e = tid + i * 256, b = e >> 4, kk4 = e & 15;
            float4 v = *(reinterpret_cast<const float4*>(X + (size_t)b * ldx + k0) + kk4);
            *reinterpret_cast<float4*>(&Xs[b * 68 + kk4 * 4]) = v;
        }
        __syncthreads();
        #pragma unroll
        for (int kk = 0; kk < 16; kk++) {
            ulonglong2 c01 = *reinterpret_cast<const ulonglong2*>(&Xs[lane * 68 + kk * 4]);
            #pragma unroll
            for (int r = 0; r < 8; r++) {
                ulonglong2 w = *reinterpret_cast<const ulonglong2*>(&Ws[(warp * 8 + r) * 68 + kk * 4]);
                FMA2(acc2[r], w.x, c01.x);
                FMA2(acc2[r], w.y, c01.y);
            }
        }
    }
    float* op = out + (size_t)blockIdx.y * HH * BB;
    #pragma unroll
    for (int r = 0; r < 8; r++) {
        float v = __uint_as_float((unsigned)acc2[r]) + __uint_as_float((unsigned)(acc2[r] >> 32));
        op[(size_t)(row0 + warp * 8 + r) * BB + lane] = v;
    }
}

// ==================== GRU gate: sum NS partials + biases ====================
__global__ void gru_gate_kernel(const float* __restrict__ A, const float* __restrict__ Bm,
                                const float* __restrict__ bih, const float* __restrict__ bhh,
                                const float* __restrict__ hprev,
                                float* __restrict__ out_hidden,
                                float* __restrict__ h_fp32,
                                __nv_bfloat16* __restrict__ hi_dst,
                                __nv_bfloat16* __restrict__ lo_dst, int xstride)
{
    int idx = blockIdx.x * 256 + threadIdx.x;
    int b = idx >> 10, i = idx & 1023;
    float ir = bih[i], iz = bih[HH + i], in_ = bih[2 * HH + i];
    float hr = bhh[i], hz = bhh[HH + i], hn = bhh[2 * HH + i];
    #pragma unroll
    for (int p = 0; p < NS; p++) {
        size_t base = (size_t)p * BB * H3 + (size_t)b * H3;
        ir  += A[base + i];
        iz  += A[base + HH + i];
        in_ += A[base + 2 * HH + i];
        hr  += Bm[base + i];
        hz  += Bm[base + HH + i];
        hn  += Bm[base + 2 * HH + i];
    }
    float r = 1.f / (1.f + expf(-(ir + hr)));
    float z = 1.f / (1.f + expf(-(iz + hz)));
    float n = tanhf(in_ + r * hn);
    float h = (1.f - z) * n + z * hprev[(size_t)b * HH + i];
    out_hidden[(size_t)b * HH + i] = h;
    if (h_fp32) h_fp32[(size_t)b * HH + i] = h;
    __nv_bfloat16 hi, lo;
    split1(h, hi, lo);
    hi_dst[(size_t)b * xstride + i] = hi;
    lo_dst[(size_t)b * xstride + i] = lo;
}

// ==================== q: sum NQ partials, transpose -> [b][j] ====================
__global__ void qfix_kernel()
{
    int idx = blockIdx.x * 256 + threadIdx.x;
    int b = idx >> 10, j = idx & 1023;
    float v = 0.f;
    #pragma unroll
    for (int p = 0; p < NQ; p++) v += g_qp[(size_t)p * HH * BB + (size_t)j * BB + b];
    g_qT[idx] = v;
}

// ==================== combine A/B/C ====================
__global__ void __launch_bounds__(128)
combine_a_kernel()
{
    __shared__ float red[4];
    const int b = blockIdx.x, tid = threadIdx.x, lane = tid & 31, warp = tid >> 5;
    float mc = g_ml[(b * NCH + tid) * 2];
    float m = mc;
    #pragma unroll
    for (int o = 16; o; o >>= 1) m = fmaxf(m, __shfl_xor_sync(0xffffffffu, m, o));
    if (!lane) red[warp] = m;
    __syncthreads();
    float M0 = fmaxf(fmaxf(red[0], red[1]), fmaxf(red[2], red[3]));
    __syncthreads();
    float w = __expf(mc - M0);
    g_wc[b * NCH + tid] = w;
    float ls = w * g_ml[(b * NCH + tid) * 2 + 1];
    #pragma unroll
    for (int o = 16; o; o >>= 1) ls += __shfl_xor_sync(0xffffffffu, ls, o);
    if (!lane) red[warp] = ls;
    __syncthreads();
    if (tid == 0) {
        float L = red[0] + red[1] + red[2] + red[3];
        g_red2[2 * b] = M0;
        g_red2[2 * b + 1] = 1.f / L;
    }
}

__global__ void __launch_bounds__(256)
combine_b_kernel()
{
    __shared__ float wsh[32];
    const int z = blockIdx.x, b = blockIdx.y, tid = threadIdx.x;
    if (tid < 32) wsh[tid] = g_wc[b * NCH + z * 32 + tid];
    __syncthreads();
    float4 acc = {0.f, 0.f, 0.f, 0.f};
    #pragma unroll 4
    for (int c = 0; c < 32; c++) {
        float wc = wsh[c];
        float4 p = *reinterpret_cast<const float4*>(
            &g_ctx_part[((size_t)(z * 32 + c) * BB + b) * HH + tid * 4]);
        acc.x = fmaf(wc, p.x, acc.x);
        acc.y = fmaf(wc, p.y, acc.y);
        acc.z = fmaf(wc, p.z, acc.z);
        acc.w = fmaf(wc, p.w, acc.w);
    }
    *reinterpret_cast<float4*>(&g_ctx2[((size_t)z * BB + b) * HH + tid * 4]) = acc;
}

__global__ void __launch_bounds__(256)
combine_c_kernel(float* __restrict__ out_ctx)
{
    const int b = blockIdx.x, tid = threadIdx.x;
    float invL = g_red2[2 * b + 1];
    float4 acc = {0.f, 0.f, 0.f, 0.f};
    #pragma unroll
    for (int z = 0; z < 4; z++) {
        float4 p = *reinterpret_cast<const float4*>(&g_ctx2[((size_t)z * BB + b) * HH + tid * 4]);
        acc.x += p.x; acc.y += p.y; acc.z += p.z; acc.w += p.w;
    }
    acc.x *= invL; acc.y *= invL; acc.z *= invL; acc.w *= invL;
    *reinterpret_cast<float4*>(&out_ctx[(size_t)b * HH + tid * 4]) = acc;
    size_t cb = (size_t)b * H2 + HH + tid * 4;
    float vv[4] = {acc.x, acc.y, acc.z, acc.w};
    #pragma unroll
    for (int k = 0; k < 4; k++) split1(vv[k], g_cathi[cb + k], g_catlo[cb + k]);
}

// ==================== vocab softmax reduce (sums 4 partials) ====================
__global__ void vocab_reduce_kernel()
{
    __shared__ float red[8];
    int b = blockIdx.x, tid = threadIdx.x, lane = tid & 31, warp = tid >> 5;
    float m = -1e30f;
    for (int v = tid; v < VV; v += 256) {
        float lg = 0.f;
        #pragma unroll
        for (int p = 0; p < 4; p++) lg += g_logits[(size_t)p * BB * VV + (size_t)b * VV + v];
        m = fmaxf(m, lg);
    }
    #pragma unroll
    for (int o = 16; o; o >>= 1) m = fmaxf(m, __shfl_xor_sync(0xffffffffu, m, o));
    if (!lane) red[warp] = m;
    __syncthreads();
    float M0 = red[0];
    #pragma unroll
    for (int i = 1; i < 8; i++) M0 = fmaxf(M0, red[i]);
    __syncthreads();
    float s = 0.f;
    for (int v = tid; v < VV; v += 256) {
        float lg = 0.f;
        #pragma unroll
        for (int p = 0; p < 4; p++) lg += g_logits[(size_t)p * BB * VV + (size_t)b * VV + v];
        s += __expf(lg - M0);
    }
    #pragma unroll
    for (int o = 16; o; o >>= 1) s += __shfl_xor_sync(0xffffffffu, s, o);
    if (!lane) red[warp] = s;
    __syncthreads();
    if (tid == 0) {
        float t = 0.f;
        #pragma unroll
        for (int i = 0; i < 8; i++) t += red[i];
        g_vred[2 * b] = M0;
        g_vred[2 * b + 1] = 1.f / t;
    }
}

__global__ void finalize_kernel(float* __restrict__ out_output, float* __restrict__ out_attn)
{
    int idx = blockIdx.x * 256 + threadIdx.x;
    if (idx < BB * VV) {
        int b = idx / VV;
        float lg = 0.f;
        #pragma unroll
        for (int p = 0; p < 4; p++) lg += g_logits[(size_t)p * BB * VV + idx];
        out_output[idx] = __expf(lg - g_vred[2 * b]) * g_vred[2 * b + 1];
    } else {
        int j = idx - BB * VV;
        int b = j >> 11;
        out_attn[j] = __expf(g_scores[j] - g_red2[2 * b]) * g_red2[2 * b + 1];
    }
}

// ==================== launch ====================
extern "C" void kernel_launch(void* const* d_in, const int* in_sizes, int n_in,
                              void* d_out, int out_size)
{
    const int*   ids  = (const int*)  d_in[0];
    const float* lctx = (const float*)d_in[1];
    const float* hid  = (const float*)d_in[2];
    const float* enc  = (const float*)d_in[3];
    const float* emb  = (const float*)d_in[4];
    const float* Wat  = (const float*)d_in[5];
    // d_in[6] b_attn: per-batch-constant score shift, softmax-invariant -> dropped
    const float* Wih0 = (const float*)d_in[7];
    const float* Whh0 = (const float*)d_in[8];
    const float* bih0 = (const float*)d_in[9];
    const float* bhh0 = (const float*)d_in[10];
    const float* Wih1 = (const float*)d_in[11];
    const float* Whh1 = (const float*)d_in[12];
    const float* bih1 = (const float*)d_in[13];
    const float* bhh1 = (const float*)d_in[14];
    const float* Wout = (const float*)d_in[15];
    const float* bout = (const float*)d_in[16];

    float* out        = (float*)d_out;
    float* out_output = out;
    float* out_ctx    = out + (size_t)BB * VV;
    float* out_hidden = out_ctx + (size_t)BB * HH;
    float* out_attn   = out_hidden + (size_t)2 * BB * HH;

    float *pA, *pB, *pH1, *pQp, *pLog;
    __nv_bfloat16 *pRh, *pRl, *pH0h, *pH0l, *pD0h, *pD0l, *pD1h, *pD1l, *pCh, *pCl;
    cudaGetSymbolAddress((void**)&pA,   g_A);
    cudaGetSymbolAddress((void**)&pB,   g_Bm);
    cudaGetSymbolAddress((void**)&pH1,  g_h1);
    cudaGetSymbolAddress((void**)&pQp,  g_qp);
    cudaGetSymbolAddress((void**)&pLog, g_logits);
    cudaGetSymbolAddress((void**)&pRh,  g_rnnhi);
    cudaGetSymbolAddress((void**)&pRl,  g_rnnlo);
    cudaGetSymbolAddress((void**)&pH0h, g_h0hi);
    cudaGetSymbolAddress((void**)&pH0l, g_h0lo);
    cudaGetSymbolAddress((void**)&pD0h, g_hid0hi);
    cudaGetSymbolAddress((void**)&pD0l, g_hid0lo);
    cudaGetSymbolAddress((void**)&pD1h, g_hid1hi);
    cudaGetSymbolAddress((void**)&pD1l, g_hid1lo);
    cudaGetSymbolAddress((void**)&pCh,  g_cathi);
    cudaGetSymbolAddress((void**)&pCl,  g_catlo);

    cudaFuncSetAttribute(attn_mega_kernel, cudaFuncAttributeMaxDynamicSharedMemorySize, ASMEM);

    const size_t PSTR = (size_t)BB * H3;

    prep_kernel<<<512, 256>>>(ids, emb, lctx, hid);
    // GRU layer 0 (fused pair, K-split NS=8)
    {
        GP a = {Wih0, H2, pRh, pRl, H2, nullptr, pA, H3, PSTR, 4};
        GP b = {Whh0, HH, pD0h, pD0l, HH, nullptr, pB, H3, PSTR, 2};
        mma_gemm_kernel<<<dim3(24, NS, 2), 256>>>(a, b);
    }
    gru_gate_kernel<<<128, 256>>>(pA, pB, bih0, bhh0, hid, out_hidden,
                                  nullptr, pH0h, pH0l, HH);
    // GRU layer 1
    {
        GP a = {Wih1, HH, pH0h, pH0l, HH, nullptr, pA, H3, PSTR, 2};
        GP b = {Whh1, HH, pD1h, pD1l, HH, nullptr, pB, H3, PSTR, 2};
        mma_gemm_kernel<<<dim3(24, NS, 2), 256>>>(a, b);
    }
    gru_gate_kernel<<<128, 256>>>(pA, pB, bih1, bhh1, hid + (size_t)BB * HH,
                                  out_hidden + (size_t)BB * HH, pH1, pCh, pCl, H2);
    // q = h1 @ W_attn (K-split NQ=8) -> sum+transpose
    gemmT_kernel<<<dim3(16, NQ), 256>>>(pH1, HH, Wat, HH, pQp, 2);
    qfix_kernel<<<128, 256>>>();
    // MEGA: attention CTAs + logits h1-half GEMM CTAs co-resident in one launch
    {
        GP lg = {Wout, H2, pCh, pCl, H2, bout, pLog, VV, (size_t)BB * VV, 8};
        attn_mega_kernel<<<NLGB + NCH * BB, 256, ASMEM>>>(lg, enc);
    }
    combine_a_kernel<<<BB, 128>>>();
    combine_b_kernel<<<dim3(4, BB), 256>>>();
    combine_c_kernel<<<BB, 256>>>(out_ctx);
    // logits ctx-half: W cols [H,2H), X = cat[:, H:2H), partials p=2,3
    {
        GP c = {Wout + HH, H2, pCh + HH, pCl + HH, H2, nullptr,
                pLog + (size_t)2 * BB * VV, VV, (size_t)BB * VV, 8};
        mma_gemm_kernel<<<dim3(250, NLG, 1), 256>>>(c, c);
    }
    vocab_reduce_kernel<<<BB, 256>>>();
    finalize_kernel<<<(BB * VV + BB * SS) / 256, 256>>>(out_output, out_attn);
}

// round 16
// speedup vs baseline: 1.0879x; 1.0126x over previous
#include <cuda_runtime.h>
#include <cuda_bf16.h>
#include <cstdint>

#define BB 32
#define HH 1024
#define SS 2048
#define VV 32000
#define H3 3072
#define H2 2048
#define ACH 16
#define NCH (SS/ACH)          // 128
#define NS 8                  // K-split partials for GRU GEMMs
#define NQ 8                  // K-split for q GEMM
#define NLG 2                 // K-split per logits half
#define ASMEM ((ACH*HH + HH + ACH) * 4)
#define GSMEM 46080

#define FMA2(acc, a, b) asm("fma.rn.f32x2 %0, %1, %2, %0;" : "+l"(acc) : "l"(a), "l"(b))

__device__ __forceinline__ void mma16816(float* d, const uint32_t* a, uint32_t b0, uint32_t b1) {
    asm volatile("mma.sync.aligned.m16n8k16.row.col.f32.bf16.bf16.f32 "
                 "{%0,%1,%2,%3}, {%4,%5,%6,%7}, {%8,%9}, {%0,%1,%2,%3};"
                 : "+f"(d[0]), "+f"(d[1]), "+f"(d[2]), "+f"(d[3])
                 : "r"(a[0]), "r"(a[1]), "r"(a[2]), "r"(a[3]), "r"(b0), "r"(b1));
}

#define LDSM4(r, a) \
    asm volatile("ldmatrix.sync.aligned.m8n8.x4.shared.b16 {%0,%1,%2,%3}, [%4];" \
                 : "=r"((r)[0]), "=r"((r)[1]), "=r"((r)[2]), "=r"((r)[3]) : "r"(a))

__device__ __forceinline__ uint32_t smem_u32(const void* p) {
    return (uint32_t)__cvta_generic_to_shared(p);
}

__device__ __forceinline__ void split1(float x, __nv_bfloat16& hi, __nv_bfloat16& lo) {
    hi = __float2bfloat16(x);
    lo = __float2bfloat16(x - __bfloat162float(hi));
}
__device__ __forceinline__ void split_pack(float a, float b, uint32_t& hi, uint32_t& lo) {
    __nv_bfloat162 h = __floats2bfloat162_rn(a, b);
    __nv_bfloat162 l2 = __floats2bfloat162_rn(a - __bfloat162float(h.x), b - __bfloat162float(h.y));
    hi = *reinterpret_cast<uint32_t*>(&h);
    lo = *reinterpret_cast<uint32_t*>(&l2);
}

// ==================== scratch ====================
__device__ __nv_bfloat16 g_rnnhi[BB * H2], g_rnnlo[BB * H2];
__device__ __nv_bfloat16 g_hid0hi[BB * HH], g_hid0lo[BB * HH];
__device__ __nv_bfloat16 g_hid1hi[BB * HH], g_hid1lo[BB * HH];
__device__ __nv_bfloat16 g_h0hi[BB * HH], g_h0lo[BB * HH];
__device__ __nv_bfloat16 g_cathi[BB * H2], g_catlo[BB * H2];
__device__ float g_h1[BB * HH];
__device__ float g_A[NS * BB * H3];
__device__ float g_Bm[NS * BB * H3];
__device__ float g_logits[4 * BB * VV];
__device__ float g_qp[NQ * HH * BB];
__device__ float g_qT[BB * HH];
__device__ float g_scores[BB * SS];
__device__ float g_ctx_part[NCH * BB * HH];
__device__ float g_ctx2[4 * BB * HH];
__device__ float g_wc[BB * NCH];
__device__ float g_ml[BB * NCH * 2];
__device__ float g_red2[BB * 2];
__device__ float g_vred[BB * 2];

// ==================== prep ====================
__global__ void prep_kernel(const int* __restrict__ ids, const float* __restrict__ emb,
                            const float* __restrict__ lctx, const float* __restrict__ hid)
{
    int idx = blockIdx.x * 256 + threadIdx.x;
    if (idx < BB * H2) {
        int b = idx >> 11, k = idx & 2047;
        float v = (k < HH) ? emb[(size_t)ids[b] * HH + k] : lctx[(size_t)b * HH + (k - HH)];
        split1(v, g_rnnhi[idx], g_rnnlo[idx]);
    } else if (idx < BB * H2 + BB * HH) {
        int j = idx - BB * H2;
        split1(hid[j], g_hid0hi[j], g_hid0lo[j]);
    } else {
        int j = idx - BB * H2 - BB * HH;
        split1(hid[BB * HH + j], g_hid1hi[j], g_hid1lo[j]);
    }
}

// ==================== HMMA GEMM body (ldmatrix fragment loads) ====================
struct GP {
    const float* W; int ldw;
    const __nv_bfloat16 *Xh, *Xl; int ldx;
    const float* bias;
    float* out; int ldo; size_t pstride; int nch;
};

__device__ __forceinline__ void gemm_body(const GP& p, int bx, int by, char* sm)
{
    __nv_bfloat16* sWh = reinterpret_cast<__nv_bfloat16*>(sm);
    __nv_bfloat16* sWl = reinterpret_cast<__nv_bfloat16*>(sm + 18432);
    __nv_bfloat16* sXh = reinterpret_cast<__nv_bfloat16*>(sm + 36864);
    __nv_bfloat16* sXl = reinterpret_cast<__nv_bfloat16*>(sm + 41472);
    const int tid = threadIdx.x, warp = tid >> 5, lane = tid & 31;
    const int t = lane & 3;
    const int row0 = bx * 128;
    const int kbase = by * p.nch * 64;
    float acc[4][4] = {};
    float4 wr[8];
    uint2 xh[2], xl[2];

    // ldmatrix lane addresses (bytes): row = lane&15, col-block = (lane>>4)*8 elems
    const uint32_t lrow = (lane & 15) * 144 + ((lane >> 4) << 4);
    const uint32_t aHi = smem_u32(sWh) + warp * 16 * 144 + lrow;
    const uint32_t aLo = aHi + 18432;
    const uint32_t bHi0 = smem_u32(sXh) + lrow;
    const uint32_t bHi1 = bHi0 + 16 * 144;
    const uint32_t bLo0 = bHi0 + 4608;
    const uint32_t bLo1 = bHi1 + 4608;

    #pragma unroll
    for (int i = 0; i < 8; i++) {
        int e = tid + i * 256, r = e >> 4, c4 = e & 15;
        wr[i] = *reinterpret_cast<const float4*>(p.W + (size_t)(row0 + r) * p.ldw + kbase + c4 * 4);
    }
    #pragma unroll
    for (int i = 0; i < 2; i++) {
        int e = tid + i * 256, r = e >> 4, c4 = e & 15;
        size_t off = (size_t)r * p.ldx + kbase + c4 * 4;
        xh[i] = *reinterpret_cast<const uint2*>(p.Xh + off);
        xl[i] = *reinterpret_cast<const uint2*>(p.Xl + off);
    }

    for (int c = 0; c < p.nch; c++) {
        __syncthreads();
        #pragma unroll
        for (int i = 0; i < 8; i++) {
            int e = tid + i * 256, r = e >> 4, c4 = e & 15;
            uint32_t h0, l0, h1, l1;
            split_pack(wr[i].x, wr[i].y, h0, l0);
            split_pack(wr[i].z, wr[i].w, h1, l1);
            *reinterpret_cast<uint2*>(&sWh[r * 72 + c4 * 4]) = make_uint2(h0, h1);
            *reinterpret_cast<uint2*>(&sWl[r * 72 + c4 * 4]) = make_uint2(l0, l1);
        }
        #pragma unroll
        for (int i = 0; i < 2; i++) {
            int e = tid + i * 256, r = e >> 4, c4 = e & 15;
            *reinterpret_cast<uint2*>(&sXh[r * 72 + c4 * 4]) = xh[i];
            *reinterpret_cast<uint2*>(&sXl[r * 72 + c4 * 4]) = xl[i];
        }
        __syncthreads();
        if (c + 1 < p.nch) {
            const int kb = kbase + (c + 1) * 64;
            #pragma unroll
            for (int i = 0; i < 8; i++) {
                int e = tid + i * 256, r = e >> 4, c4 = e & 15;
                wr[i] = *reinterpret_cast<const float4*>(p.W + (size_t)(row0 + r) * p.ldw + kb + c4 * 4);
            }
            #pragma unroll
            for (int i = 0; i < 2; i++) {
                int e = tid + i * 256, r = e >> 4, c4 = e & 15;
                size_t off = (size_t)r * p.ldx + kb + c4 * 4;
                xh[i] = *reinterpret_cast<const uint2*>(p.Xh + off);
                xl[i] = *reinterpret_cast<const uint2*>(p.Xl + off);
            }
        }
        #pragma unroll
        for (int ks = 0; ks < 4; ks++) {
            const uint32_t ko = ks * 32;   // bytes
            uint32_t ah[4], al[4], b0h[4], b1h[4], b0l[4], b1l[4];
            LDSM4(ah, aHi + ko);
            LDSM4(al, aLo + ko);
            LDSM4(b0h, bHi0 + ko);
            LDSM4(b1h, bHi1 + ko);
            LDSM4(b0l, bLo0 + ko);
            LDSM4(b1l, bLo1 + ko);
            // nt0: {b0[0],b0[2]}  nt1: {b0[1],b0[3]}  nt2: {b1[0],b1[2]}  nt3: {b1[1],b1[3]}
            mma16816(acc[0], ah, b0h[0], b0h[2]);
            mma16816(acc[0], ah, b0l[0], b0l[2]);
            mma16816(acc[0], al, b0h[0], b0h[2]);
            mma16816(acc[1], ah, b0h[1], b0h[3]);
            mma16816(acc[1], ah, b0l[1], b0l[3]);
            mma16816(acc[1], al, b0h[1], b0h[3]);
            mma16816(acc[2], ah, b1h[0], b1h[2]);
            mma16816(acc[2], ah, b1l[0], b1l[2]);
            mma16816(acc[2], al, b1h[0], b1h[2]);
            mma16816(acc[3], ah, b1h[1], b1h[3]);
            mma16816(acc[3], ah, b1l[1], b1l[3]);
            mma16816(acc[3], al, b1h[1], b1h[3]);
        }
    }
    __syncthreads();
    float* T = reinterpret_cast<float*>(sWh);
    const int g = lane >> 2;
    #pragma unroll
    for (int nt = 0; nt < 4; nt++) {
        int b0 = nt * 8 + t * 2;
        int j0 = warp * 16 + g;
        T[b0 * 132 + j0]           = acc[nt][0];
        T[(b0 + 1) * 132 + j0]     = acc[nt][1];
        T[b0 * 132 + j0 + 8]       = acc[nt][2];
        T[(b0 + 1) * 132 + j0 + 8] = acc[nt][3];
    }
    __syncthreads();
    float* outp = p.out + (size_t)by * p.pstride;
    const float* bias = p.bias;
    #pragma unroll
    for (int i = 0; i < 4; i++) {
        int b = (tid >> 5) + i * 8;
        int j = lane * 4;
        float4 v = *reinterpret_cast<const float4*>(&T[b * 132 + j]);
        if (bias && by == 0) {
            v.x += bias[row0 + j];
            v.y += bias[row0 + j + 1];
            v.z += bias[row0 + j + 2];
            v.w += bias[row0 + j + 3];
        }
        *reinterpret_cast<float4*>(&outp[(size_t)b * p.ldo + row0 + j]) = v;
    }
}

// standalone GEMM kernel (GRU pairs + logits ctx-half)
__global__ void __launch_bounds__(256, 2)
mma_gemm_kernel(GP p0, GP p1)
{
    __shared__ alignas(16) char sm[GSMEM];
    const GP& p = blockIdx.z ? p1 : p0;
    gemm_body(p, blockIdx.x, blockIdx.y, sm);
}

// ==================== MEGA: logits h1-half GEMM CTAs + attention CTAs ====================
#define NLGB (250 * NLG)
__global__ void __launch_bounds__(256)
attn_mega_kernel(GP lg, const float* __restrict__ enc)
{
    extern __shared__ char dsm[];
    if (blockIdx.x < NLGB) {
        gemm_body(lg, blockIdx.x % 250, blockIdx.x / 250, dsm);
        return;
    }
    float* tile = reinterpret_cast<float*>(dsm);
    float* qs   = tile + ACH * HH;
    float* sc   = qs + HH;
    const int bx = blockIdx.x - NLGB;
    const int sp = bx & (NCH - 1), b = bx >> 7;
    const int tid = threadIdx.x, warp = tid >> 5, lane = tid & 31;
    *reinterpret_cast<float4*>(&qs[tid * 4]) =
        *reinterpret_cast<const float4*>(&g_qT[(size_t)b * HH + tid * 4]);
    __syncthreads();
    for (int s = warp; s < ACH; s += 8) {
        const float4* ep = reinterpret_cast<const float4*>(
            enc + ((size_t)b * SS + (size_t)sp * ACH + s) * HH);
        float acc = 0.f;
        #pragma unroll
        for (int j = 0; j < 8; j++) {
            float4 ev = ep[lane + 32 * j];
            float4 qv = *reinterpret_cast<const float4*>(&qs[(lane + 32 * j) * 4]);
            *reinterpret_cast<float4*>(&tile[s * HH + (lane + 32 * j) * 4]) = ev;
            acc = fmaf(ev.x, qv.x, fmaf(ev.y, qv.y, fmaf(ev.z, qv.z, fmaf(ev.w, qv.w, acc))));
        }
        #pragma unroll
        for (int o = 16; o; o >>= 1) acc += __shfl_xor_sync(0xffffffffu, acc, o);
        if (lane == 0) {
            sc[s] = acc;
            g_scores[(size_t)b * SS + sp * ACH + s] = acc;
        }
    }
    __syncthreads();
    float m = sc[0];
    #pragma unroll
    for (int s = 1; s < ACH; s++) m = fmaxf(m, sc[s]);
    float l = 0.f;
    float4 ctx = {0.f, 0.f, 0.f, 0.f};
    #pragma unroll
    for (int s = 0; s < ACH; s++) {
        float w = __expf(sc[s] - m);
        l += w;
        float4 ev = *reinterpret_cast<const float4*>(&tile[s * HH + tid * 4]);
        ctx.x = fmaf(w, ev.x, ctx.x);
        ctx.y = fmaf(w, ev.y, ctx.y);
        ctx.z = fmaf(w, ev.z, ctx.z);
        ctx.w = fmaf(w, ev.w, ctx.w);
    }
    *reinterpret_cast<float4*>(&g_ctx_part[((size_t)sp * BB + b) * HH + tid * 4]) = ctx;
    if (tid == 0) {
        g_ml[(b * NCH + sp) * 2] = m;
        g_ml[(b * NCH + sp) * 2 + 1] = l;
    }
}

// ==================== FFMA2 GEMM, W reduction-major (q = h1 @ W_attn) ====================
__global__ void __launch_bounds__(256)
gemmT_kernel(const float* __restrict__ X, int ldx,
             const float* __restrict__ Wm, int M,
             float* __restrict__ out, int n_chunks)
{
    __shared__ float Ws[64 * 68];
    __shared__ float Xs[32 * 68];
    const int tid = threadIdx.x, warp = tid >> 5, lane = tid & 31;
    const int row0 = blockIdx.x * 64;
    const int kbase = blockIdx.y * n_chunks * 64;
    unsigned long long acc2[8] = {0, 0, 0, 0, 0, 0, 0, 0};

    for (int c = 0; c < n_chunks; c++) {
        const int k0 = kbase + c * 64;
        __syncthreads();
        #pragma unroll
        for (int i = 0; i < 4; i++) {
            int e = tid + i * 256, r4 = e & 15, kk = e >> 4;
            float4 w = *reinterpret_cast<const float4*>(Wm + (size_t)(k0 + kk) * M + row0 + r4 * 4);
            Ws[(r4 * 4 + 0) * 68 + kk] = w.x;
            Ws[(r4 * 4 + 1) * 68 + kk] = w.y;
            Ws[(r4 * 4 + 2) * 68 + kk] = w.z;
            Ws[(r4 * 4 + 3) * 68 + kk] = w.w;
        }
        #pragma unroll
        for (int i = 0; i < 2; i++) {
            int e = tid + i * 256, b = e >> 4, kk4 = e & 15;
            float4 v = *(reinterpret_cast<const float4*>(X + (size_t)b * ldx + k0) + kk4);
            *reinterpret_cast<float4*>(&Xs[b * 68 + kk4 * 4]) = v;
        }
        __syncthreads();
        #pragma unroll
        for (int kk = 0; kk < 16; kk++) {
            ulonglong2 c01 = *reinterpret_cast<const ulonglong2*>(&Xs[lane * 68 + kk * 4]);
            #pragma unroll
            for (int r = 0; r < 8; r++) {
                ulonglong2 w = *reinterpret_cast<const ulonglong2*>(&Ws[(warp * 8 + r) * 68 + kk * 4]);
                FMA2(acc2[r], w.x, c01.x);
                FMA2(acc2[r], w.y, c01.y);
            }
        }
    }
    float* op = out + (size_t)blockIdx.y * HH * BB;
    #pragma unroll
    for (int r = 0; r < 8; r++) {
        float v = __uint_as_float((unsigned)acc2[r]) + __uint_as_float((unsigned)(acc2[r] >> 32));
        op[(size_t)(row0 + warp * 8 + r) * BB + lane] = v;
    }
}

// ==================== GRU gate: sum NS partials + biases ====================
__global__ void gru_gate_kernel(const float* __restrict__ A, const float* __restrict__ Bm,
                                const float* __restrict__ bih, const float* __restrict__ bhh,
                                const float* __restrict__ hprev,
                                float* __restrict__ out_hidden,
                                float* __restrict__ h_fp32,
                                __nv_bfloat16* __restrict__ hi_dst,
                                __nv_bfloat16* __restrict__ lo_dst, int xstride)
{
    int idx = blockIdx.x * 256 + threadIdx.x;
    int b = idx >> 10, i = idx & 1023;
    float ir = bih[i], iz = bih[HH + i], in_ = bih[2 * HH + i];
    float hr = bhh[i], hz = bhh[HH + i], hn = bhh[2 * HH + i];
    #pragma unroll
    for (int p = 0; p < NS; p++) {
        size_t base = (size_t)p * BB * H3 + (size_t)b * H3;
        ir  += A[base + i];
        iz  += A[base + HH + i];
        in_ += A[base + 2 * HH + i];
        hr  += Bm[base + i];
        hz  += Bm[base + HH + i];
        hn  += Bm[base + 2 * HH + i];
    }
    float r = 1.f / (1.f + expf(-(ir + hr)));
    float z = 1.f / (1.f + expf(-(iz + hz)));
    float n = tanhf(in_ + r * hn);
    float h = (1.f - z) * n + z * hprev[(size_t)b * HH + i];
    out_hidden[(size_t)b * HH + i] = h;
    if (h_fp32) h_fp32[(size_t)b * HH + i] = h;
    __nv_bfloat16 hi, lo;
    split1(h, hi, lo);
    hi_dst[(size_t)b * xstride + i] = hi;
    lo_dst[(size_t)b * xstride + i] = lo;
}

// ==================== q: sum NQ partials, transpose -> [b][j] ====================
__global__ void qfix_kernel()
{
    int idx = blockIdx.x * 256 + threadIdx.x;
    int b = idx >> 10, j = idx & 1023;
    float v = 0.f;
    #pragma unroll
    for (int p = 0; p < NQ; p++) v += g_qp[(size_t)p * HH * BB + (size_t)j * BB + b];
    g_qT[idx] = v;
}

// ==================== combine A/B/C ====================
__global__ void __launch_bounds__(128)
combine_a_kernel()
{
    __shared__ float red[4];
    const int b = blockIdx.x, tid = threadIdx.x, lane = tid & 31, warp = tid >> 5;
    float mc = g_ml[(b * NCH + tid) * 2];
    float m = mc;
    #pragma unroll
    for (int o = 16; o; o >>= 1) m = fmaxf(m, __shfl_xor_sync(0xffffffffu, m, o));
    if (!lane) red[warp] = m;
    __syncthreads();
    float M0 = fmaxf(fmaxf(red[0], red[1]), fmaxf(red[2], red[3]));
    __syncthreads();
    float w = __expf(mc - M0);
    g_wc[b * NCH + tid] = w;
    float ls = w * g_ml[(b * NCH + tid) * 2 + 1];
    #pragma unroll
    for (int o = 16; o; o >>= 1) ls += __shfl_xor_sync(0xffffffffu, ls, o);
    if (!lane) red[warp] = ls;
    __syncthreads();
    if (tid == 0) {
        float L = red[0] + red[1] + red[2] + red[3];
        g_red2[2 * b] = M0;
        g_red2[2 * b + 1] = 1.f / L;
    }
}

__global__ void __launch_bounds__(256)
combine_b_kernel()
{
    __shared__ float wsh[32];
    const int z = blockIdx.x, b = blockIdx.y, tid = threadIdx.x;
    if (tid < 32) wsh[tid] = g_wc[b * NCH + z * 32 + tid];
    __syncthreads();
    float4 acc = {0.f, 0.f, 0.f, 0.f};
    #pragma unroll 4
    for (int c = 0; c < 32; c++) {
        float wc = wsh[c];
        float4 p = *reinterpret_cast<const float4*>(
            &g_ctx_part[((size_t)(z * 32 + c) * BB + b) * HH + tid * 4]);
        acc.x = fmaf(wc, p.x, acc.x);
        acc.y = fmaf(wc, p.y, acc.y);
        acc.z = fmaf(wc, p.z, acc.z);
        acc.w = fmaf(wc, p.w, acc.w);
    }
    *reinterpret_cast<float4*>(&g_ctx2[((size_t)z * BB + b) * HH + tid * 4]) = acc;
}

__global__ void __launch_bounds__(256)
combine_c_kernel(float* __restrict__ out_ctx)
{
    const int b = blockIdx.x, tid = threadIdx.x;
    float invL = g_red2[2 * b + 1];
    float4 acc = {0.f, 0.f, 0.f, 0.f};
    #pragma unroll
    for (int z = 0; z < 4; z++) {
        float4 p = *reinterpret_cast<const float4*>(&g_ctx2[((size_t)z * BB + b) * HH + tid * 4]);
        acc.x += p.x; acc.y += p.y; acc.z += p.z; acc.w += p.w;
    }
    acc.x *= invL; acc.y *= invL; acc.z *= invL; acc.w *= invL;
    *reinterpret_cast<float4*>(&out_ctx[(size_t)b * HH + tid * 4]) = acc;
    size_t cb = (size_t)b * H2 + HH + tid * 4;
    float vv[4] = {acc.x, acc.y, acc.z, acc.w};
    #pragma unroll
    for (int k = 0; k < 4; k++) split1(vv[k], g_cathi[cb + k], g_catlo[cb + k]);
}

// ==================== vocab softmax reduce (sums 4 partials) ====================
__global__ void vocab_reduce_kernel()
{
    __shared__ float red[8];
    int b = blockIdx.x, tid = threadIdx.x, lane = tid & 31, warp = tid >> 5;
    float m = -1e30f;
    for (int v = tid; v < VV; v += 256) {
        float lg = 0.f;
        #pragma unroll
        for (int p = 0; p < 4; p++) lg += g_logits[(size_t)p * BB * VV + (size_t)b * VV + v];
        m = fmaxf(m, lg);
    }
    #pragma unroll
    for (int o = 16; o; o >>= 1) m = fmaxf(m, __shfl_xor_sync(0xffffffffu, m, o));
    if (!lane) red[warp] = m;
    __syncthreads();
    float M0 = red[0];
    #pragma unroll
    for (int i = 1; i < 8; i++) M0 = fmaxf(M0, red[i]);
    __syncthreads();
    float s = 0.f;
    for (int v = tid; v < VV; v += 256) {
        float lg = 0.f;
        #pragma unroll
        for (int p = 0; p < 4; p++) lg += g_logits[(size_t)p * BB * VV + (size_t)b * VV + v];
        s += __expf(lg - M0);
    }
    #pragma unroll
    for (int o = 16; o; o >>= 1) s += __shfl_xor_sync(0xffffffffu, s, o);
    if (!lane) red[warp] = s;
    __syncthreads();
    if (tid == 0) {
        float t = 0.f;
        #pragma unroll
        for (int i = 0; i < 8; i++) t += red[i];
        g_vred[2 * b] = M0;
        g_vred[2 * b + 1] = 1.f / t;
    }
}

__global__ void finalize_kernel(float* __restrict__ out_output, float* __restrict__ out_attn)
{
    int idx = blockIdx.x * 256 + threadIdx.x;
    if (idx < BB * VV) {
        int b = idx / VV;
        float lg = 0.f;
        #pragma unroll
        for (int p = 0; p < 4; p++) lg += g_logits[(size_t)p * BB * VV + idx];
        out_output[idx] = __expf(lg - g_vred[2 * b]) * g_vred[2 * b + 1];
    } else {
        int j = idx - BB * VV;
        int b = j >> 11;
        out_attn[j] = __expf(g_scores[j] - g_red2[2 * b]) * g_red2[2 * b + 1];
    }
}

// ==================== launch ====================
extern "C" void kernel_launch(void* const* d_in, const int* in_sizes, int n_in,
                              void* d_out, int out_size)
{
    const int*   ids  = (const int*)  d_in[0];
    const float* lctx = (const float*)d_in[1];
    const float* hid  = (const float*)d_in[2];
    const float* enc  = (const float*)d_in[3];
    const float* emb  = (const float*)d_in[4];
    const float* Wat  = (const float*)d_in[5];
    // d_in[6] b_attn: per-batch-constant score shift, softmax-invariant -> dropped
    const float* Wih0 = (const float*)d_in[7];
    const float* Whh0 = (const float*)d_in[8];
    const float* bih0 = (const float*)d_in[9];
    const float* bhh0 = (const float*)d_in[10];
    const float* Wih1 = (const float*)d_in[11];
    const float* Whh1 = (const float*)d_in[12];
    const float* bih1 = (const float*)d_in[13];
    const float* bhh1 = (const float*)d_in[14];
    const float* Wout = (const float*)d_in[15];
    const float* bout = (const float*)d_in[16];

    float* out        = (float*)d_out;
    float* out_output = out;
    float* out_ctx    = out + (size_t)BB * VV;
    float* out_hidden = out_ctx + (size_t)BB * HH;
    float* out_attn   = out_hidden + (size_t)2 * BB * HH;

    float *pA, *pB, *pH1, *pQp, *pLog;
    __nv_bfloat16 *pRh, *pRl, *pH0h, *pH0l, *pD0h, *pD0l, *pD1h, *pD1l, *pCh, *pCl;
    cudaGetSymbolAddress((void**)&pA,   g_A);
    cudaGetSymbolAddress((void**)&pB,   g_Bm);
    cudaGetSymbolAddress((void**)&pH1,  g_h1);
    cudaGetSymbolAddress((void**)&pQp,  g_qp);
    cudaGetSymbolAddress((void**)&pLog, g_logits);
    cudaGetSymbolAddress((void**)&pRh,  g_rnnhi);
    cudaGetSymbolAddress((void**)&pRl,  g_rnnlo);
    cudaGetSymbolAddress((void**)&pH0h, g_h0hi);
    cudaGetSymbolAddress((void**)&pH0l, g_h0lo);
    cudaGetSymbolAddress((void**)&pD0h, g_hid0hi);
    cudaGetSymbolAddress((void**)&pD0l, g_hid0lo);
    cudaGetSymbolAddress((void**)&pD1h, g_hid1hi);
    cudaGetSymbolAddress((void**)&pD1l, g_hid1lo);
    cudaGetSymbolAddress((void**)&pCh,  g_cathi);
    cudaGetSymbolAddress((void**)&pCl,  g_catlo);

    cudaFuncSetAttribute(attn_mega_kernel, cudaFuncAttributeMaxDynamicSharedMemorySize, ASMEM);

    const size_t PSTR = (size_t)BB * H3;

    prep_kernel<<<512, 256>>>(ids, emb, lctx, hid);
    // GRU layer 0 (fused pair, K-split NS=8)
    {
        GP a = {Wih0, H2, pRh, pRl, H2, nullptr, pA, H3, PSTR, 4};
        GP b = {Whh0, HH, pD0h, pD0l, HH, nullptr, pB, H3, PSTR, 2};
        mma_gemm_kernel<<<dim3(24, NS, 2), 256>>>(a, b);
    }
    gru_gate_kernel<<<128, 256>>>(pA, pB, bih0, bhh0, hid, out_hidden,
                                  nullptr, pH0h, pH0l, HH);
    // GRU layer 1
    {
        GP a = {Wih1, HH, pH0h, pH0l, HH, nullptr, pA, H3, PSTR, 2};
        GP b = {Whh1, HH, pD1h, pD1l, HH, nullptr, pB, H3, PSTR, 2};
        mma_gemm_kernel<<<dim3(24, NS, 2), 256>>>(a, b);
    }
    gru_gate_kernel<<<128, 256>>>(pA, pB, bih1, bhh1, hid + (size_t)BB * HH,
                                  out_hidden + (size_t)BB * HH, pH1, pCh, pCl, H2);
    // q = h1 @ W_attn (K-split NQ=8) -> sum+transpose
    gemmT_kernel<<<dim3(16, NQ), 256>>>(pH1, HH, Wat, HH, pQp, 2);
    qfix_kernel<<<128, 256>>>();
    // MEGA: attention CTAs + logits h1-half GEMM CTAs co-resident in one launch
    {
        GP lg = {Wout, H2, pCh, pCl, H2, bout, pLog, VV, (size_t)BB * VV, 8};
        attn_mega_kernel<<<NLGB + NCH * BB, 256, ASMEM>>>(lg, enc);
    }
    combine_a_kernel<<<BB, 128>>>();
    combine_b_kernel<<<dim3(4, BB), 256>>>();
    combine_c_kernel<<<BB, 256>>>(out_ctx);
    // logits ctx-half: W cols [H,2H), X = cat[:, H:2H), partials p=2,3
    {
        GP c = {Wout + HH, H2, pCh + HH, pCl + HH, H2, nullptr,
                pLog + (size_t)2 * BB * VV, VV, (size_t)BB * VV, 8};
        mma_gemm_kernel<<<dim3(250, NLG, 1), 256>>>(c, c);
    }
    vocab_reduce_kernel<<<BB, 256>>>();
    finalize_kernel<<<(BB * VV + BB * SS) / 256, 256>>>(out_output, out_attn);
}